// round 15
// baseline (speedup 1.0000x reference)
#include <cuda_runtime.h>

#define FULLMASK 0xffffffffu

#define TT 128
#define DD 32
#define HH 64
#define G3 192

#define WARPS 8
#define PAIRS 4
#define PB 8          // batches per warp pair
#define FB 4          // batches finalized per warp
#define THREADS 256
#define BATCH_PER_BLOCK 32
#define NBLOCKS 128

typedef unsigned long long ull;

// ---- smem layout (floats) ----
#define O_WIH0T 0                        // [32][192] transposed
#define O_WHH0T (O_WIH0T + DD * G3)      // [64][192]
#define O_WIH1T (O_WHH0T + HH * G3)      // [64][192]
#define O_WHH1T (O_WIH1T + HH * G3)      // [64][192]
#define O_BI0   (O_WHH1T + HH * G3)
#define O_BH0   (O_BI0 + G3)
#define O_BI1   (O_BH0 + G3)
#define O_BH1   (O_BI1 + G3)
#define O_PBUF  (O_BH1 + G3)             // per pair: h1[8][64], h2[8][64], x[8][32]
#define PBUF_FLOATS (PB * HH + PB * HH + PB * DD)   // 1280
#define O_EX    (O_PBUF + PAIRS * PBUF_FLOATS)
#define EX_ULL_PER_PAIR (2 * FB * 4 * 32)           // 1024 ull
#define SMEM_FLOATS (O_EX + PAIRS * EX_ULL_PER_PAIR * 2)
#define SMEM_BYTES (SMEM_FLOATS * 4)

__device__ __forceinline__ float sigmoid_f(float v) {
    float e = __expf(-v);
    return __fdividef(1.0f, 1.0f + e);
}
__device__ __forceinline__ float tanh_f(float v) {
    float e = __expf(-2.0f * v);
    return __fdividef(1.0f - e, 1.0f + e);
}

// ---- packed f32x2 helpers ----
__device__ __forceinline__ void fma2(ull& d, ull a, ull b) {
    asm("fma.rn.f32x2 %0, %1, %2, %0;" : "+l"(d) : "l"(a), "l"(b));
}
__device__ __forceinline__ ull add2(ull a, ull b) {
    ull r;
    asm("add.rn.f32x2 %0, %1, %2;" : "=l"(r) : "l"(a), "l"(b));
    return r;
}
__device__ __forceinline__ ull splat2(float v) {
    ull r;
    asm("mov.b64 %0, {%1, %1};" : "=l"(r) : "f"(v));
    return r;
}
__device__ __forceinline__ ull pack2(float lo, float hi) {
    ull r;
    asm("mov.b64 %0, {%1, %2};" : "=l"(r) : "f"(lo), "f"(hi));
    return r;
}
__device__ __forceinline__ float2 unpack2(ull v) {
    float2 f;
    asm("mov.b64 {%0, %1}, %2;" : "=f"(f.x), "=f"(f.y) : "l"(v));
    return f;
}

__device__ __forceinline__ void pair_bar(int pair) {
    asm volatile("bar.sync %0, %1;" :: "r"(pair + 1), "r"(64) : "memory");
}

// k-split gemv segment: KH k-elements starting at the caller-applied offset.
// wt: ull(float2) view of transposed weights, already offset to k0 row.
// vb: input vector buffer [PB][L], already offset by k0 within the row.
// Lane owns packed unit pair (2*lane, 2*lane+1); accumulates 3 gates x PB.
template <int L, int KH>
__device__ __forceinline__ void mv_ks(
    const ull* __restrict__ wt, const float* __restrict__ vb, int lane,
    ull a0[PB], ull a1[PB], ull a2[PB])
{
#pragma unroll 2
    for (int g = 0; g < KH / 4; ++g) {
        const ull* r0 = wt + (4 * g + 0) * 96;
        const ull* r1 = wt + (4 * g + 1) * 96;
        const ull* r2 = wt + (4 * g + 2) * 96;
        const ull* r3 = wt + (4 * g + 3) * 96;
        ull w0r = r0[lane], w0z = r0[32 + lane], w0n = r0[64 + lane];
        ull w1r = r1[lane], w1z = r1[32 + lane], w1n = r1[64 + lane];
        ull w2r = r2[lane], w2z = r2[32 + lane], w2n = r2[64 + lane];
        ull w3r = r3[lane], w3z = r3[32 + lane], w3n = r3[64 + lane];
#pragma unroll
        for (int b = 0; b < PB; ++b) {
            // broadcast LDS.128: 4 consecutive k-values, same address all lanes
            float4 hv = *(const float4*)(vb + b * L + 4 * g);
            ull s0 = splat2(hv.x), s1 = splat2(hv.y);
            ull s2 = splat2(hv.z), s3 = splat2(hv.w);
            fma2(a0[b], w0r, s0); fma2(a1[b], w0z, s0); fma2(a2[b], w0n, s0);
            fma2(a0[b], w1r, s1); fma2(a1[b], w1z, s1); fma2(a2[b], w1n, s1);
            fma2(a0[b], w2r, s2); fma2(a1[b], w2z, s2); fma2(a2[b], w2n, s2);
            fma2(a0[b], w3r, s3); fma2(a1[b], w3z, s3); fma2(a2[b], w3n, s3);
        }
    }
}

extern __shared__ float smem[];

__global__ void __launch_bounds__(THREADS, 1)
gru_fused_kernel(const float* __restrict__ x,
                 const float* __restrict__ Wih0, const float* __restrict__ Whh0,
                 const float* __restrict__ bih0, const float* __restrict__ bhh0,
                 const float* __restrict__ Wih1, const float* __restrict__ Whh1,
                 const float* __restrict__ bih1, const float* __restrict__ bhh1,
                 const float* __restrict__ fcw, const float* __restrict__ fcb,
                 float* __restrict__ out)
{
    const int tid = threadIdx.x;

    // ---- cooperative load: transpose weights into smem ----
    for (int i = tid; i < G3 * DD; i += THREADS) {
        int j = i / DD, k = i % DD;
        smem[O_WIH0T + k * G3 + j] = Wih0[i];
    }
    for (int i = tid; i < G3 * HH; i += THREADS) {
        int j = i / HH, k = i % HH;
        smem[O_WHH0T + k * G3 + j] = Whh0[i];
        smem[O_WIH1T + k * G3 + j] = Wih1[i];
        smem[O_WHH1T + k * G3 + j] = Whh1[i];
    }
    for (int i = tid; i < G3; i += THREADS) {
        smem[O_BI0 + i] = bih0[i];
        smem[O_BH0 + i] = bhh0[i];
        smem[O_BI1 + i] = bih1[i];
        smem[O_BH1 + i] = bhh1[i];
    }
    // zero all pair buffers (h1, h2, x)
    for (int i = tid; i < PAIRS * PBUF_FLOATS; i += THREADS)
        smem[O_PBUF + i] = 0.0f;
    __syncthreads();

    const int warp = tid >> 5;
    const int lane = tid & 31;
    const int side = warp & 1;          // 0: k-low half, 1: k-high half
    const int pair = warp >> 1;
    const int myb  = side * FB;         // batches this warp finalizes
    const int bb   = blockIdx.x * BATCH_PER_BLOCK + pair * PB;
    const int u0 = 2 * lane;
    const int u1 = u0 + 1;
    const int k0d = side * (DD / 2);    // 0 or 16
    const int k0h = side * (HH / 2);    // 0 or 32

    float* h1b  = smem + O_PBUF + pair * PBUF_FLOATS;   // [8][64]
    float* h2b  = h1b + PB * HH;                         // [8][64]
    float* xbuf = h2b + PB * HH;                         // [8][32]
    ull* exu = (ull*)(smem + O_EX) + pair * EX_ULL_PER_PAIR;

    // packed bias constants
    const ull br0  = pack2(smem[O_BI0 + u0] + smem[O_BH0 + u0],
                           smem[O_BI0 + u1] + smem[O_BH0 + u1]);
    const ull bz0  = pack2(smem[O_BI0 + 64 + u0] + smem[O_BH0 + 64 + u0],
                           smem[O_BI0 + 64 + u1] + smem[O_BH0 + 64 + u1]);
    const ull bnx0 = pack2(smem[O_BI0 + 128 + u0], smem[O_BI0 + 128 + u1]);
    const ull bnh0 = pack2(smem[O_BH0 + 128 + u0], smem[O_BH0 + 128 + u1]);
    const ull br1  = pack2(smem[O_BI1 + u0] + smem[O_BH1 + u0],
                           smem[O_BI1 + u1] + smem[O_BH1 + u1]);
    const ull bz1  = pack2(smem[O_BI1 + 64 + u0] + smem[O_BH1 + 64 + u0],
                           smem[O_BI1 + 64 + u1] + smem[O_BH1 + 64 + u1]);
    const ull bnx1 = pack2(smem[O_BI1 + 128 + u0], smem[O_BI1 + 128 + u1]);
    const ull bnh1 = pack2(smem[O_BH1 + 128 + u0], smem[O_BH1 + 128 + u1]);

    const ull* wih0 = (const ull*)(smem + O_WIH0T) + k0d * 96;
    const ull* whh0 = (const ull*)(smem + O_WHH0T) + k0h * 96;
    const ull* wih1 = (const ull*)(smem + O_WIH1T) + k0h * 96;
    const ull* whh1 = (const ull*)(smem + O_WHH1T) + k0h * 96;
    const float* xv  = xbuf + k0d;
    const float* h1v = h1b + k0h;
    const float* h2v = h2b + k0h;

    // stage x_0 for this warp's 4 batches
#pragma unroll
    for (int i = 0; i < FB; ++i)
        xbuf[(myb + i) * DD + lane] = x[(size_t)(bb + myb + i) * (TT * DD) + lane];
    __syncthreads();

    float h2A[FB], h2B[FB];
#pragma unroll
    for (int i = 0; i < FB; ++i) { h2A[i] = 0.f; h2B[i] = 0.f; }

    for (int t = 0; t < TT; ++t) {
        // prefetch next timestep's x (this warp's 4 batches)
        float xn[FB];
        if (t + 1 < TT) {
#pragma unroll
            for (int i = 0; i < FB; ++i)
                xn[i] = x[(size_t)(bb + myb + i) * (TT * DD) + (t + 1) * DD + lane];
        }

        ull ar[PB], az[PB], anx[PB], anh[PB];

        // ---------------- layer 1 (k-half partials for all 8 batches) ----------
#pragma unroll
        for (int b = 0; b < PB; ++b) { ar[b] = 0; az[b] = 0; anx[b] = 0; anh[b] = 0; }
        mv_ks<DD, DD / 2>(wih0, xv, lane, ar, az, anx);
        mv_ks<HH, HH / 2>(whh0, h1v, lane, ar, az, anh);

        // exchange: hand partner its batches' partials
#pragma unroll
        for (int i = 0; i < FB; ++i) {
            int ob = (FB - myb) + i;  // partner's batches: 4-myb = other base
            exu[((side * FB + i) * 4 + 0) * 32 + lane] = ar[ob];
            exu[((side * FB + i) * 4 + 1) * 32 + lane] = az[ob];
            exu[((side * FB + i) * 4 + 2) * 32 + lane] = anx[ob];
            exu[((side * FB + i) * 4 + 3) * 32 + lane] = anh[ob];
        }
        pair_bar(pair);
#pragma unroll
        for (int i = 0; i < FB; ++i) {
            int b = myb + i;
            int os = (1 - side) * FB + i;
            ar[b]  = add2(ar[b],  exu[(os * 4 + 0) * 32 + lane]);
            az[b]  = add2(az[b],  exu[(os * 4 + 1) * 32 + lane]);
            anx[b] = add2(anx[b], exu[(os * 4 + 2) * 32 + lane]);
            anh[b] = add2(anh[b], exu[(os * 4 + 3) * 32 + lane]);
        }

#pragma unroll
        for (int i = 0; i < FB; ++i) {
            int b = myb + i;
            float2 rv = unpack2(add2(ar[b], br0));
            float2 zv = unpack2(add2(az[b], bz0));
            float2 nx = unpack2(add2(anx[b], bnx0));
            float2 nh = unpack2(add2(anh[b], bnh0));
            float2 hold = *(const float2*)(h1b + b * HH + u0);
            float r0 = sigmoid_f(rv.x), r1 = sigmoid_f(rv.y);
            float z0 = sigmoid_f(zv.x), z1 = sigmoid_f(zv.y);
            float n0 = tanh_f(nx.x + r0 * nh.x);
            float n1 = tanh_f(nx.y + r1 * nh.y);
            float hA = n0 + z0 * (hold.x - n0);
            float hB = n1 + z1 * (hold.y - n1);
            *(float2*)(h1b + b * HH + u0) = make_float2(hA, hB);
        }
        pair_bar(pair);

        // ---------------- layer 2 ----------------
#pragma unroll
        for (int b = 0; b < PB; ++b) { ar[b] = 0; az[b] = 0; anx[b] = 0; anh[b] = 0; }
        mv_ks<HH, HH / 2>(wih1, h1v, lane, ar, az, anx);
        mv_ks<HH, HH / 2>(whh1, h2v, lane, ar, az, anh);

#pragma unroll
        for (int i = 0; i < FB; ++i) {
            int ob = (FB - myb) + i;
            exu[((side * FB + i) * 4 + 0) * 32 + lane] = ar[ob];
            exu[((side * FB + i) * 4 + 1) * 32 + lane] = az[ob];
            exu[((side * FB + i) * 4 + 2) * 32 + lane] = anx[ob];
            exu[((side * FB + i) * 4 + 3) * 32 + lane] = anh[ob];
        }
        pair_bar(pair);
#pragma unroll
        for (int i = 0; i < FB; ++i) {
            int b = myb + i;
            int os = (1 - side) * FB + i;
            ar[b]  = add2(ar[b],  exu[(os * 4 + 0) * 32 + lane]);
            az[b]  = add2(az[b],  exu[(os * 4 + 1) * 32 + lane]);
            anx[b] = add2(anx[b], exu[(os * 4 + 2) * 32 + lane]);
            anh[b] = add2(anh[b], exu[(os * 4 + 3) * 32 + lane]);
        }

#pragma unroll
        for (int i = 0; i < FB; ++i) {
            int b = myb + i;
            float2 rv = unpack2(add2(ar[b], br1));
            float2 zv = unpack2(add2(az[b], bz1));
            float2 nx = unpack2(add2(anx[b], bnx1));
            float2 nh = unpack2(add2(anh[b], bnh1));
            float r0 = sigmoid_f(rv.x), r1 = sigmoid_f(rv.y);
            float z0 = sigmoid_f(zv.x), z1 = sigmoid_f(zv.y);
            float n0 = tanh_f(nx.x + r0 * nh.x);
            float n1 = tanh_f(nx.y + r1 * nh.y);
            float hA = n0 + z0 * (h2A[i] - n0);
            float hB = n1 + z1 * (h2B[i] - n1);
            h2A[i] = hA; h2B[i] = hB;
            *(float2*)(h2b + b * HH + u0) = make_float2(hA, hB);
        }

        // stage next x (safe: this step's mv32 reads are done)
        if (t + 1 < TT) {
#pragma unroll
            for (int i = 0; i < FB; ++i)
                xbuf[(myb + i) * DD + lane] = xn[i];
        }
        pair_bar(pair);
    }

    // ---- final FC ----
    float w0 = fcw[u0], w1 = fcw[u1];
    float p[FB];
#pragma unroll
    for (int i = 0; i < FB; ++i)
        p[i] = h2A[i] * w0 + h2B[i] * w1;
#pragma unroll
    for (int off = 16; off > 0; off >>= 1) {
#pragma unroll
        for (int i = 0; i < FB; ++i)
            p[i] += __shfl_xor_sync(FULLMASK, p[i], off);
    }
    if (lane == 0) {
        float bias = fcb[0];
#pragma unroll
        for (int i = 0; i < FB; ++i)
            out[bb + myb + i] = p[i] + bias;
    }
}

extern "C" void kernel_launch(void* const* d_in, const int* in_sizes, int n_in,
                              void* d_out, int out_size)
{
    const float* x    = (const float*)d_in[0];
    const float* Wih0 = (const float*)d_in[1];
    const float* Whh0 = (const float*)d_in[2];
    const float* bih0 = (const float*)d_in[3];
    const float* bhh0 = (const float*)d_in[4];
    const float* Wih1 = (const float*)d_in[5];
    const float* Whh1 = (const float*)d_in[6];
    const float* bih1 = (const float*)d_in[7];
    const float* bhh1 = (const float*)d_in[8];
    const float* fcw  = (const float*)d_in[9];
    const float* fcb  = (const float*)d_in[10];
    float* out = (float*)d_out;

    cudaFuncSetAttribute(gru_fused_kernel,
                         cudaFuncAttributeMaxDynamicSharedMemorySize, SMEM_BYTES);

    gru_fused_kernel<<<NBLOCKS, THREADS, SMEM_BYTES>>>(
        x, Wih0, Whh0, bih0, bhh0, Wih1, Whh1, bih1, bhh1, fcw, fcb, out);
}

// round 16
// speedup vs baseline: 1.4501x; 1.4501x over previous
#include <cuda_runtime.h>

#define FULLMASK 0xffffffffu

#define TT 128
#define DD 32
#define HH 64
#define G3 192

#define WARPS 8
#define PAIRS 4
#define PB 8          // batches per warp pair
#define FB 4          // batches finalized per warp
#define THREADS 256
#define BATCH_PER_BLOCK 32
#define NBLOCKS 128

typedef unsigned long long ull;

// ---- smem layout (floats) ----
#define O_WIH0T 0                        // [32][192] transposed
#define O_WHH0T (O_WIH0T + DD * G3)      // [64][192]
#define O_WIH1T (O_WHH0T + HH * G3)      // [64][192]
#define O_WHH1T (O_WIH1T + HH * G3)      // [64][192]
#define O_BI0   (O_WHH1T + HH * G3)
#define O_BH0   (O_BI0 + G3)
#define O_BI1   (O_BH0 + G3)
#define O_BH1   (O_BI1 + G3)
#define O_PBUF  (O_BH1 + G3)             // per pair: h1[8][64], h2[8][64], x[8][32]
#define PBUF_FLOATS (PB * HH + PB * HH + PB * DD)   // 1280
#define O_EX    (O_PBUF + PAIRS * PBUF_FLOATS)
#define EX_ULL_PER_PAIR 1024             // two 512-ull regions (RZ / N)
#define SMEM_FLOATS (O_EX + PAIRS * EX_ULL_PER_PAIR * 2)
#define SMEM_BYTES (SMEM_FLOATS * 4)

__device__ __forceinline__ float sigmoid_f(float v) {
    float e = __expf(-v);
    return __fdividef(1.0f, 1.0f + e);
}
__device__ __forceinline__ float tanh_f(float v) {
    float e = __expf(-2.0f * v);
    return __fdividef(1.0f - e, 1.0f + e);
}

// ---- packed f32x2 helpers ----
__device__ __forceinline__ void fma2(ull& d, ull a, ull b) {
    asm("fma.rn.f32x2 %0, %1, %2, %0;" : "+l"(d) : "l"(a), "l"(b));
}
__device__ __forceinline__ ull add2(ull a, ull b) {
    ull r;
    asm("add.rn.f32x2 %0, %1, %2;" : "=l"(r) : "l"(a), "l"(b));
    return r;
}
__device__ __forceinline__ ull splat2(float v) {
    ull r;
    asm("mov.b64 %0, {%1, %1};" : "=l"(r) : "f"(v));
    return r;
}
__device__ __forceinline__ ull pack2(float lo, float hi) {
    ull r;
    asm("mov.b64 %0, {%1, %2};" : "=l"(r) : "f"(lo), "f"(hi));
    return r;
}
__device__ __forceinline__ float2 unpack2(ull v) {
    float2 f;
    asm("mov.b64 {%0, %1}, %2;" : "=f"(f.x), "=f"(f.y) : "l"(v));
    return f;
}

__device__ __forceinline__ void pair_bar(int pair) {
    asm volatile("bar.sync %0, %1;" :: "r"(pair + 1), "r"(64) : "memory");
}

// Two-gate (r,z) k-split gemv over KH k-elements. wt pre-offset to this warp's
// k-half; gate columns at [lane] (r) and [32+lane] (z). 16 ull accs live.
template <int L, int KH>
__device__ __forceinline__ void mv2(
    const ull* __restrict__ wt, const float* __restrict__ vb, int lane,
    ull a0[PB], ull a1[PB])
{
#pragma unroll 2
    for (int g = 0; g < KH / 4; ++g) {
        const ull* r0 = wt + (4 * g + 0) * 96;
        const ull* r1 = wt + (4 * g + 1) * 96;
        const ull* r2 = wt + (4 * g + 2) * 96;
        const ull* r3 = wt + (4 * g + 3) * 96;
        ull w0a = r0[lane], w0b = r0[32 + lane];
        ull w1a = r1[lane], w1b = r1[32 + lane];
        ull w2a = r2[lane], w2b = r2[32 + lane];
        ull w3a = r3[lane], w3b = r3[32 + lane];
#pragma unroll
        for (int b = 0; b < PB; ++b) {
            float4 hv = *(const float4*)(vb + b * L + 4 * g);
            ull s0 = splat2(hv.x), s1 = splat2(hv.y);
            ull s2 = splat2(hv.z), s3 = splat2(hv.w);
            fma2(a0[b], w0a, s0); fma2(a1[b], w0b, s0);
            fma2(a0[b], w1a, s1); fma2(a1[b], w1b, s1);
            fma2(a0[b], w2a, s2); fma2(a1[b], w2b, s2);
            fma2(a0[b], w3a, s3); fma2(a1[b], w3b, s3);
        }
    }
}

// One-gate (n) k-split gemv; gate column at [64+lane]. 8 ull accs live.
template <int L, int KH>
__device__ __forceinline__ void mv1(
    const ull* __restrict__ wt, const float* __restrict__ vb, int lane,
    ull a0[PB])
{
#pragma unroll 2
    for (int g = 0; g < KH / 4; ++g) {
        ull w0 = (wt + (4 * g + 0) * 96)[64 + lane];
        ull w1 = (wt + (4 * g + 1) * 96)[64 + lane];
        ull w2 = (wt + (4 * g + 2) * 96)[64 + lane];
        ull w3 = (wt + (4 * g + 3) * 96)[64 + lane];
#pragma unroll
        for (int b = 0; b < PB; ++b) {
            float4 hv = *(const float4*)(vb + b * L + 4 * g);
            fma2(a0[b], w0, splat2(hv.x));
            fma2(a0[b], w1, splat2(hv.y));
            fma2(a0[b], w2, splat2(hv.z));
            fma2(a0[b], w3, splat2(hv.w));
        }
    }
}

extern __shared__ float smem[];

__global__ void __launch_bounds__(THREADS, 1)
gru_fused_kernel(const float* __restrict__ x,
                 const float* __restrict__ Wih0, const float* __restrict__ Whh0,
                 const float* __restrict__ bih0, const float* __restrict__ bhh0,
                 const float* __restrict__ Wih1, const float* __restrict__ Whh1,
                 const float* __restrict__ bih1, const float* __restrict__ bhh1,
                 const float* __restrict__ fcw, const float* __restrict__ fcb,
                 float* __restrict__ out)
{
    const int tid = threadIdx.x;

    // ---- cooperative load: transpose weights into smem ----
    for (int i = tid; i < G3 * DD; i += THREADS) {
        int j = i / DD, k = i % DD;
        smem[O_WIH0T + k * G3 + j] = Wih0[i];
    }
    for (int i = tid; i < G3 * HH; i += THREADS) {
        int j = i / HH, k = i % HH;
        smem[O_WHH0T + k * G3 + j] = Whh0[i];
        smem[O_WIH1T + k * G3 + j] = Wih1[i];
        smem[O_WHH1T + k * G3 + j] = Whh1[i];
    }
    for (int i = tid; i < G3; i += THREADS) {
        smem[O_BI0 + i] = bih0[i];
        smem[O_BH0 + i] = bhh0[i];
        smem[O_BI1 + i] = bih1[i];
        smem[O_BH1 + i] = bhh1[i];
    }
    for (int i = tid; i < PAIRS * PBUF_FLOATS; i += THREADS)
        smem[O_PBUF + i] = 0.0f;
    __syncthreads();

    const int warp = tid >> 5;
    const int lane = tid & 31;
    const int side = warp & 1;          // 0: k-low half, 1: k-high half
    const int pair = warp >> 1;
    const int myb  = side * FB;         // batches this warp finalizes
    const int bb   = blockIdx.x * BATCH_PER_BLOCK + pair * PB;
    const int u0 = 2 * lane;
    const int u1 = u0 + 1;
    const int k0d = side * (DD / 2);
    const int k0h = side * (HH / 2);

    float* h1b  = smem + O_PBUF + pair * PBUF_FLOATS;   // [8][64]
    float* h2b  = h1b + PB * HH;                         // [8][64]
    float* xbuf = h2b + PB * HH;                         // [8][32]
    ull* ex0 = (ull*)(smem + O_EX) + pair * EX_ULL_PER_PAIR;
    ull* ex1 = ex0 + 512;

    // packed bias constants
    const ull br0  = pack2(smem[O_BI0 + u0] + smem[O_BH0 + u0],
                           smem[O_BI0 + u1] + smem[O_BH0 + u1]);
    const ull bz0  = pack2(smem[O_BI0 + 64 + u0] + smem[O_BH0 + 64 + u0],
                           smem[O_BI0 + 64 + u1] + smem[O_BH0 + 64 + u1]);
    const ull bnx0 = pack2(smem[O_BI0 + 128 + u0], smem[O_BI0 + 128 + u1]);
    const ull bnh0 = pack2(smem[O_BH0 + 128 + u0], smem[O_BH0 + 128 + u1]);
    const ull br1  = pack2(smem[O_BI1 + u0] + smem[O_BH1 + u0],
                           smem[O_BI1 + u1] + smem[O_BH1 + u1]);
    const ull bz1  = pack2(smem[O_BI1 + 64 + u0] + smem[O_BH1 + 64 + u0],
                           smem[O_BI1 + 64 + u1] + smem[O_BH1 + 64 + u1]);
    const ull bnx1 = pack2(smem[O_BI1 + 128 + u0], smem[O_BI1 + 128 + u1]);
    const ull bnh1 = pack2(smem[O_BH1 + 128 + u0], smem[O_BH1 + 128 + u1]);

    const ull* wih0 = (const ull*)(smem + O_WIH0T) + k0d * 96;
    const ull* whh0 = (const ull*)(smem + O_WHH0T) + k0h * 96;
    const ull* wih1 = (const ull*)(smem + O_WIH1T) + k0h * 96;
    const ull* whh1 = (const ull*)(smem + O_WHH1T) + k0h * 96;
    const float* xv  = xbuf + k0d;
    const float* h1v = h1b + k0h;
    const float* h2v = h2b + k0h;

    // stage x_0 for this warp's 4 batches
#pragma unroll
    for (int i = 0; i < FB; ++i)
        xbuf[(myb + i) * DD + lane] = x[(size_t)(bb + myb + i) * (TT * DD) + lane];
    __syncthreads();

    float h2A[FB], h2B[FB];
#pragma unroll
    for (int i = 0; i < FB; ++i) { h2A[i] = 0.f; h2B[i] = 0.f; }

    for (int t = 0; t < TT; ++t) {
        float xn[FB];
        if (t + 1 < TT) {
#pragma unroll
            for (int i = 0; i < FB; ++i)
                xn[i] = x[(size_t)(bb + myb + i) * (TT * DD) + (t + 1) * DD + lane];
        }

        ull a0[PB], a1[PB];
        float rsA[FB], rsB[FB], zsA[FB], zsB[FB];

        // ======== layer 1, phase R/Z ========
#pragma unroll
        for (int b = 0; b < PB; ++b) { a0[b] = 0; a1[b] = 0; }
        mv2<DD, DD / 2>(wih0, xv, lane, a0, a1);
        mv2<HH, HH / 2>(whh0, h1v, lane, a0, a1);
#pragma unroll
        for (int i = 0; i < FB; ++i) {
            int ob = (FB - myb) + i;
            ex0[((side * FB + i) * 2 + 0) * 32 + lane] = a0[ob];
            ex0[((side * FB + i) * 2 + 1) * 32 + lane] = a1[ob];
        }
        pair_bar(pair);
#pragma unroll
        for (int i = 0; i < FB; ++i) {
            int b = myb + i;
            int os = (1 - side) * FB + i;
            float2 rv = unpack2(add2(add2(a0[b], ex0[(os * 2 + 0) * 32 + lane]), br0));
            float2 zv = unpack2(add2(add2(a1[b], ex0[(os * 2 + 1) * 32 + lane]), bz0));
            rsA[i] = sigmoid_f(rv.x); rsB[i] = sigmoid_f(rv.y);
            zsA[i] = sigmoid_f(zv.x); zsB[i] = sigmoid_f(zv.y);
        }

        // ======== layer 1, phase N ========
#pragma unroll
        for (int b = 0; b < PB; ++b) { a0[b] = 0; a1[b] = 0; }
        mv1<DD, DD / 2>(wih0, xv, lane, a0);   // nx
        mv1<HH, HH / 2>(whh0, h1v, lane, a1);  // nh
#pragma unroll
        for (int i = 0; i < FB; ++i) {
            int ob = (FB - myb) + i;
            ex1[((side * FB + i) * 2 + 0) * 32 + lane] = a0[ob];
            ex1[((side * FB + i) * 2 + 1) * 32 + lane] = a1[ob];
        }
        pair_bar(pair);
#pragma unroll
        for (int i = 0; i < FB; ++i) {
            int b = myb + i;
            int os = (1 - side) * FB + i;
            float2 nx = unpack2(add2(add2(a0[b], ex1[(os * 2 + 0) * 32 + lane]), bnx0));
            float2 nh = unpack2(add2(add2(a1[b], ex1[(os * 2 + 1) * 32 + lane]), bnh0));
            float n0 = tanh_f(nx.x + rsA[i] * nh.x);
            float n1 = tanh_f(nx.y + rsB[i] * nh.y);
            float2 hold = *(const float2*)(h1b + b * HH + u0);
            float hA = n0 + zsA[i] * (hold.x - n0);
            float hB = n1 + zsB[i] * (hold.y - n1);
            *(float2*)(h1b + b * HH + u0) = make_float2(hA, hB);
        }
        pair_bar(pair);   // h1 writes visible before layer-2 gemvs

        // ======== layer 2, phase R/Z ========
#pragma unroll
        for (int b = 0; b < PB; ++b) { a0[b] = 0; a1[b] = 0; }
        mv2<HH, HH / 2>(wih1, h1v, lane, a0, a1);
        mv2<HH, HH / 2>(whh1, h2v, lane, a0, a1);
#pragma unroll
        for (int i = 0; i < FB; ++i) {
            int ob = (FB - myb) + i;
            ex0[((side * FB + i) * 2 + 0) * 32 + lane] = a0[ob];
            ex0[((side * FB + i) * 2 + 1) * 32 + lane] = a1[ob];
        }
        pair_bar(pair);
#pragma unroll
        for (int i = 0; i < FB; ++i) {
            int b = myb + i;
            int os = (1 - side) * FB + i;
            float2 rv = unpack2(add2(add2(a0[b], ex0[(os * 2 + 0) * 32 + lane]), br1));
            float2 zv = unpack2(add2(add2(a1[b], ex0[(os * 2 + 1) * 32 + lane]), bz1));
            rsA[i] = sigmoid_f(rv.x); rsB[i] = sigmoid_f(rv.y);
            zsA[i] = sigmoid_f(zv.x); zsB[i] = sigmoid_f(zv.y);
        }

        // ======== layer 2, phase N ========
#pragma unroll
        for (int b = 0; b < PB; ++b) { a0[b] = 0; a1[b] = 0; }
        mv1<HH, HH / 2>(wih1, h1v, lane, a0);  // nx
        mv1<HH, HH / 2>(whh1, h2v, lane, a1);  // nh
#pragma unroll
        for (int i = 0; i < FB; ++i) {
            int ob = (FB - myb) + i;
            ex1[((side * FB + i) * 2 + 0) * 32 + lane] = a0[ob];
            ex1[((side * FB + i) * 2 + 1) * 32 + lane] = a1[ob];
        }
        pair_bar(pair);
#pragma unroll
        for (int i = 0; i < FB; ++i) {
            int b = myb + i;
            int os = (1 - side) * FB + i;
            float2 nx = unpack2(add2(add2(a0[b], ex1[(os * 2 + 0) * 32 + lane]), bnx1));
            float2 nh = unpack2(add2(add2(a1[b], ex1[(os * 2 + 1) * 32 + lane]), bnh1));
            float n0 = tanh_f(nx.x + rsA[i] * nh.x);
            float n1 = tanh_f(nx.y + rsB[i] * nh.y);
            float hA = n0 + zsA[i] * (h2A[i] - n0);
            float hB = n1 + zsB[i] * (h2B[i] - n1);
            h2A[i] = hA; h2B[i] = hB;
            *(float2*)(h2b + b * HH + u0) = make_float2(hA, hB);
        }

        if (t + 1 < TT) {
#pragma unroll
            for (int i = 0; i < FB; ++i)
                xbuf[(myb + i) * DD + lane] = xn[i];
        }
        pair_bar(pair);   // h2/x writes visible before next step
    }

    // ---- final FC ----
    float w0 = fcw[u0], w1 = fcw[u1];
    float p[FB];
#pragma unroll
    for (int i = 0; i < FB; ++i)
        p[i] = h2A[i] * w0 + h2B[i] * w1;
#pragma unroll
    for (int off = 16; off > 0; off >>= 1) {
#pragma unroll
        for (int i = 0; i < FB; ++i)
            p[i] += __shfl_xor_sync(FULLMASK, p[i], off);
    }
    if (lane == 0) {
        float bias = fcb[0];
#pragma unroll
        for (int i = 0; i < FB; ++i)
            out[bb + myb + i] = p[i] + bias;
    }
}

extern "C" void kernel_launch(void* const* d_in, const int* in_sizes, int n_in,
                              void* d_out, int out_size)
{
    const float* x    = (const float*)d_in[0];
    const float* Wih0 = (const float*)d_in[1];
    const float* Whh0 = (const float*)d_in[2];
    const float* bih0 = (const float*)d_in[3];
    const float* bhh0 = (const float*)d_in[4];
    const float* Wih1 = (const float*)d_in[5];
    const float* Whh1 = (const float*)d_in[6];
    const float* bih1 = (const float*)d_in[7];
    const float* bhh1 = (const float*)d_in[8];
    const float* fcw  = (const float*)d_in[9];
    const float* fcb  = (const float*)d_in[10];
    float* out = (float*)d_out;

    cudaFuncSetAttribute(gru_fused_kernel,
                         cudaFuncAttributeMaxDynamicSharedMemorySize, SMEM_BYTES);

    gru_fused_kernel<<<NBLOCKS, THREADS, SMEM_BYTES>>>(
        x, Wih0, Whh0, bih0, bhh0, Wih1, Whh1, bih1, bhh1, fcw, fcb, out);
}

// round 17
// speedup vs baseline: 1.8405x; 1.2692x over previous
#include <cuda_runtime.h>

#define FULLMASK 0xffffffffu

#define TT 128
#define DD 32
#define HH 64
#define G3 192

#define WARPS 8
#define RB 4                 // batches per warp
#define THREADS (WARPS * 32)           // 256
#define BATCH_PER_BLOCK (WARPS * RB)   // 32
#define NBLOCKS 128                    // 4096 / 32

typedef unsigned long long ull;

// ---- smem layout (floats) ----
#define O_WIH0T 0                        // [32][192] transposed
#define O_WHH0T (O_WIH0T + DD * G3)      // [64][192]
#define O_WIH1T (O_WHH0T + HH * G3)      // [64][192]
#define O_WHH1T (O_WIH1T + HH * G3)      // [64][192]
#define O_BI0   (O_WHH1T + HH * G3)
#define O_BH0   (O_BI0 + G3)
#define O_BI1   (O_BH0 + G3)
#define O_BH1   (O_BI1 + G3)
#define O_HBUF  (O_BH1 + G3)             // per warp: h1[RB][64], h2[RB][64], x[RB][32]
#define HBUF_PER_WARP (2 * RB * HH + RB * DD)
#define SMEM_FLOATS (O_HBUF + WARPS * HBUF_PER_WARP)
#define SMEM_BYTES (SMEM_FLOATS * 4)

__device__ __forceinline__ float sigmoid_f(float v) {
    float e = __expf(-v);
    return __fdividef(1.0f, 1.0f + e);
}
__device__ __forceinline__ float tanh_f(float v) {
    float e = __expf(-2.0f * v);
    return __fdividef(1.0f - e, 1.0f + e);
}

// ---- packed f32x2 helpers ----
__device__ __forceinline__ void fma2(ull& d, ull a, ull b) {
    asm("fma.rn.f32x2 %0, %1, %2, %0;" : "+l"(d) : "l"(a), "l"(b));
}
__device__ __forceinline__ ull splat2(float v) {
    ull r;
    asm("mov.b64 %0, {%1, %1};" : "=l"(r) : "f"(v));
    return r;
}
__device__ __forceinline__ ull pack2(float lo, float hi) {
    ull r;
    asm("mov.b64 %0, {%1, %2};" : "=l"(r) : "f"(lo), "f"(hi));
    return r;
}
__device__ __forceinline__ float2 unpack2(ull v) {
    float2 f;
    asm("mov.b64 {%0, %1}, %2;" : "=f"(f.x), "=f"(f.y) : "l"(v));
    return f;
}

// gemv over an L-long vector held in warp-private smem buffer vb[RB][L].
// w2: ull(float2) view of transposed weights ([k][192] floats -> rows of 96).
// Lane owns packed unit pair (2*lane, 2*lane+1); accumulates 3 gates x RB.
// Processes 4 k-rows per group; input read as ONE broadcast LDS.128 per batch.
template <int L>
__device__ __forceinline__ void mv_f2(
    const ull* __restrict__ w2, const float* __restrict__ vb, int lane,
    ull ar[RB], ull az[RB], ull an[RB])
{
#pragma unroll 2
    for (int g = 0; g < L / 4; ++g) {
        const ull* r0 = w2 + (4 * g + 0) * 96;
        const ull* r1 = w2 + (4 * g + 1) * 96;
        const ull* r2 = w2 + (4 * g + 2) * 96;
        const ull* r3 = w2 + (4 * g + 3) * 96;
        ull w0r = r0[lane], w0z = r0[32 + lane], w0n = r0[64 + lane];
        ull w1r = r1[lane], w1z = r1[32 + lane], w1n = r1[64 + lane];
        ull w2r = r2[lane], w2z = r2[32 + lane], w2n = r2[64 + lane];
        ull w3r = r3[lane], w3z = r3[32 + lane], w3n = r3[64 + lane];
#pragma unroll
        for (int b = 0; b < RB; ++b) {
            // broadcast LDS.128: 4 consecutive k-values, same address all lanes
            float4 hv = *(const float4*)(vb + b * L + 4 * g);
            ull s0 = splat2(hv.x);
            ull s1 = splat2(hv.y);
            ull s2 = splat2(hv.z);
            ull s3 = splat2(hv.w);
            fma2(ar[b], w0r, s0); fma2(az[b], w0z, s0); fma2(an[b], w0n, s0);
            fma2(ar[b], w1r, s1); fma2(az[b], w1z, s1); fma2(an[b], w1n, s1);
            fma2(ar[b], w2r, s2); fma2(az[b], w2z, s2); fma2(an[b], w2n, s2);
            fma2(ar[b], w3r, s3); fma2(az[b], w3z, s3); fma2(an[b], w3n, s3);
        }
    }
}

extern __shared__ float smem[];

__global__ void __launch_bounds__(THREADS, 1)
gru_fused_kernel(const float* __restrict__ x,
                 const float* __restrict__ Wih0, const float* __restrict__ Whh0,
                 const float* __restrict__ bih0, const float* __restrict__ bhh0,
                 const float* __restrict__ Wih1, const float* __restrict__ Whh1,
                 const float* __restrict__ bih1, const float* __restrict__ bhh1,
                 const float* __restrict__ fcw, const float* __restrict__ fcb,
                 float* __restrict__ out)
{
    const int tid = threadIdx.x;

    // ---- cooperative load: transpose weights into smem ----
    for (int i = tid; i < G3 * DD; i += THREADS) {
        int j = i / DD, k = i % DD;
        smem[O_WIH0T + k * G3 + j] = Wih0[i];
    }
    for (int i = tid; i < G3 * HH; i += THREADS) {
        int j = i / HH, k = i % HH;
        smem[O_WHH0T + k * G3 + j] = Whh0[i];
        smem[O_WIH1T + k * G3 + j] = Wih1[i];
        smem[O_WHH1T + k * G3 + j] = Whh1[i];
    }
    for (int i = tid; i < G3; i += THREADS) {
        smem[O_BI0 + i] = bih0[i];
        smem[O_BH0 + i] = bhh0[i];
        smem[O_BI1 + i] = bih1[i];
        smem[O_BH1 + i] = bhh1[i];
    }
    __syncthreads();

    const int warp = tid >> 5;
    const int lane = tid & 31;
    const int b0 = blockIdx.x * BATCH_PER_BLOCK + warp * RB;
    const int u0 = 2 * lane;
    const int u1 = u0 + 1;

    float* h1b  = smem + O_HBUF + warp * HBUF_PER_WARP;  // [RB][64]
    float* h2b  = h1b + RB * HH;                          // [RB][64]
    float* xbuf = h2b + RB * HH;                          // [RB][32]

    // zero warp-private state buffers
    for (int i = lane; i < HBUF_PER_WARP; i += 32)
        h1b[i] = 0.0f;
    __syncwarp();

    // packed bias constants (unit pair of this lane)
    const ull br0  = pack2(smem[O_BI0 + u0] + smem[O_BH0 + u0],
                           smem[O_BI0 + u1] + smem[O_BH0 + u1]);
    const ull bz0  = pack2(smem[O_BI0 + 64 + u0] + smem[O_BH0 + 64 + u0],
                           smem[O_BI0 + 64 + u1] + smem[O_BH0 + 64 + u1]);
    const ull bnx0 = pack2(smem[O_BI0 + 128 + u0], smem[O_BI0 + 128 + u1]);
    const ull bnh0 = pack2(smem[O_BH0 + 128 + u0], smem[O_BH0 + 128 + u1]);

    const ull br1  = pack2(smem[O_BI1 + u0] + smem[O_BH1 + u0],
                           smem[O_BI1 + u1] + smem[O_BH1 + u1]);
    const ull bz1  = pack2(smem[O_BI1 + 64 + u0] + smem[O_BH1 + 64 + u0],
                           smem[O_BI1 + 64 + u1] + smem[O_BH1 + 64 + u1]);
    const ull bnx1 = pack2(smem[O_BI1 + 128 + u0], smem[O_BI1 + 128 + u1]);
    const ull bnh1 = pack2(smem[O_BH1 + 128 + u0], smem[O_BH1 + 128 + u1]);

    const ull* wih0 = (const ull*)(smem + O_WIH0T);
    const ull* whh0 = (const ull*)(smem + O_WHH0T);
    const ull* wih1 = (const ull*)(smem + O_WIH1T);
    const ull* whh1 = (const ull*)(smem + O_WHH1T);

    // x prefetch registers
    float xc[RB], xn[RB];
#pragma unroll
    for (int b = 0; b < RB; ++b)
        xc[b] = x[(size_t)(b0 + b) * (TT * DD) + lane];

    float h2A[RB], h2B[RB];   // layer-2 state for the lane's own unit pair
#pragma unroll
    for (int b = 0; b < RB; ++b) { h2A[b] = 0.f; h2B[b] = 0.f; }

    for (int t = 0; t < TT; ++t) {
        // stage current x into warp-private smem for broadcast reads
#pragma unroll
        for (int b = 0; b < RB; ++b)
            xbuf[b * DD + lane] = xc[b];
        __syncwarp();

        // prefetch next timestep's x
        if (t + 1 < TT) {
#pragma unroll
            for (int b = 0; b < RB; ++b)
                xn[b] = x[(size_t)(b0 + b) * (TT * DD) + (t + 1) * DD + lane];
        }

        ull ar[RB], az[RB], anx[RB], anh[RB];

        // ---------------- layer 1 ----------------
#pragma unroll
        for (int b = 0; b < RB; ++b) {
            ar[b] = br0; az[b] = bz0; anx[b] = bnx0; anh[b] = bnh0;
        }
        mv_f2<DD>(wih0, xbuf, lane, ar, az, anx);
        mv_f2<HH>(whh0, h1b, lane, ar, az, anh);

#pragma unroll
        for (int b = 0; b < RB; ++b) {
            float2 rv = unpack2(ar[b]);
            float2 zv = unpack2(az[b]);
            float2 nx = unpack2(anx[b]);
            float2 nh = unpack2(anh[b]);
            float2 hold = *(const float2*)(h1b + b * HH + u0);  // own pair
            float r0 = sigmoid_f(rv.x), r1 = sigmoid_f(rv.y);
            float z0 = sigmoid_f(zv.x), z1 = sigmoid_f(zv.y);
            float n0 = tanh_f(nx.x + r0 * nh.x);
            float n1 = tanh_f(nx.y + r1 * nh.y);
            float hA = n0 + z0 * (hold.x - n0);
            float hB = n1 + z1 * (hold.y - n1);
            *(float2*)(h1b + b * HH + u0) = make_float2(hA, hB);
        }
        __syncwarp();

        // ---------------- layer 2 ----------------
#pragma unroll
        for (int b = 0; b < RB; ++b) {
            ar[b] = br1; az[b] = bz1; anx[b] = bnx1; anh[b] = bnh1;
        }
        // whh1 first: reads h2b, independent of the h1 update just stored —
        // gives the h1 STS->LDS broadcast extra distance before wih1 reads it.
        mv_f2<HH>(whh1, h2b, lane, ar, az, anh);
        mv_f2<HH>(wih1, h1b, lane, ar, az, anx);

#pragma unroll
        for (int b = 0; b < RB; ++b) {
            float2 rv = unpack2(ar[b]);
            float2 zv = unpack2(az[b]);
            float2 nx = unpack2(anx[b]);
            float2 nh = unpack2(anh[b]);
            float r0 = sigmoid_f(rv.x), r1 = sigmoid_f(rv.y);
            float z0 = sigmoid_f(zv.x), z1 = sigmoid_f(zv.y);
            float n0 = tanh_f(nx.x + r0 * nh.x);
            float n1 = tanh_f(nx.y + r1 * nh.y);
            float hA = n0 + z0 * (h2A[b] - n0);
            float hB = n1 + z1 * (h2B[b] - n1);
            h2A[b] = hA; h2B[b] = hB;
            *(float2*)(h2b + b * HH + u0) = make_float2(hA, hB);
        }
        __syncwarp();

#pragma unroll
        for (int b = 0; b < RB; ++b) xc[b] = xn[b];
    }

    // ---- final FC ----
    float w0 = fcw[u0], w1 = fcw[u1];
    float p[RB];
#pragma unroll
    for (int b = 0; b < RB; ++b)
        p[b] = h2A[b] * w0 + h2B[b] * w1;
#pragma unroll
    for (int off = 16; off > 0; off >>= 1) {
#pragma unroll
        for (int b = 0; b < RB; ++b)
            p[b] += __shfl_xor_sync(FULLMASK, p[b], off);
    }
    if (lane == 0) {
        float bias = fcb[0];
#pragma unroll
        for (int b = 0; b < RB; ++b)
            out[b0 + b] = p[b] + bias;
    }
}

extern "C" void kernel_launch(void* const* d_in, const int* in_sizes, int n_in,
                              void* d_out, int out_size)
{
    const float* x    = (const float*)d_in[0];
    const float* Wih0 = (const float*)d_in[1];
    const float* Whh0 = (const float*)d_in[2];
    const float* bih0 = (const float*)d_in[3];
    const float* bhh0 = (const float*)d_in[4];
    const float* Wih1 = (const float*)d_in[5];
    const float* Whh1 = (const float*)d_in[6];
    const float* bih1 = (const float*)d_in[7];
    const float* bhh1 = (const float*)d_in[8];
    const float* fcw  = (const float*)d_in[9];
    const float* fcb  = (const float*)d_in[10];
    float* out = (float*)d_out;

    cudaFuncSetAttribute(gru_fused_kernel,
                         cudaFuncAttributeMaxDynamicSharedMemorySize, SMEM_BYTES);

    gru_fused_kernel<<<NBLOCKS, THREADS, SMEM_BYTES>>>(
        x, Wih0, Whh0, bih0, bhh0, Wih1, Whh1, bih1, bhh1, fcw, fcb, out);
}